// round 2
// baseline (speedup 1.0000x reference)
#include <cuda_runtime.h>
#include <math.h>

#define B_  2
#define L_  512
#define H_  128
#define NH_ 2
#define DH_ 64

// Scratch (allocation-free rule: __device__ globals)
__device__ float g_Q[B_ * L_ * H_];
__device__ float g_K[B_ * L_ * H_];
__device__ float g_V[B_ * L_ * H_];
__device__ float g_O[B_ * L_ * H_];

#define ROWS_PER_BLK 8

// ---------------------------------------------------------------------------
// Kernel 1: fused QKV projections
//   Q = query @ Wq^T + bq
//   K = key   @ Wk^T + bk + E_PK[pos]
//   V = value @ Wv^T + bv + E_PV[pos]
// block = 128 threads (one per output channel o), 8 rows per block.
// ---------------------------------------------------------------------------
__global__ __launch_bounds__(128) void qkv_kernel(
    const float* __restrict__ query, const float* __restrict__ key,
    const float* __restrict__ value,
    const float* __restrict__ Wq, const float* __restrict__ bq,
    const float* __restrict__ Wk, const float* __restrict__ bk,
    const float* __restrict__ Wv, const float* __restrict__ bv,
    const float* __restrict__ E_PK, const float* __restrict__ E_PV,
    const int* __restrict__ poss)
{
    __shared__ float xq[ROWS_PER_BLK][H_];
    __shared__ float xk[ROWS_PER_BLK][H_];
    __shared__ float xv[ROWS_PER_BLK][H_];

    const int r0 = blockIdx.x * ROWS_PER_BLK;
    const int o  = threadIdx.x;   // 0..127

    #pragma unroll
    for (int rr = 0; rr < ROWS_PER_BLK; rr++) {
        int r = r0 + rr;
        xq[rr][o] = query[r * H_ + o];
        xk[rr][o] = key  [r * H_ + o];
        xv[rr][o] = value[r * H_ + o];
    }
    __syncthreads();

    float acc[ROWS_PER_BLK];

    // ---- Q ----
    {
        float b = bq[o];
        #pragma unroll
        for (int rr = 0; rr < ROWS_PER_BLK; rr++) acc[rr] = b;
        const float* w = Wq + o * H_;
        #pragma unroll 4
        for (int k = 0; k < H_; k++) {
            float wv = w[k];
            #pragma unroll
            for (int rr = 0; rr < ROWS_PER_BLK; rr++) acc[rr] += xq[rr][k] * wv;
        }
        #pragma unroll
        for (int rr = 0; rr < ROWS_PER_BLK; rr++) g_Q[(r0 + rr) * H_ + o] = acc[rr];
    }

    // ---- K ----
    {
        #pragma unroll
        for (int rr = 0; rr < ROWS_PER_BLK; rr++) {
            int p = poss[r0 + rr];
            acc[rr] = bk[o] + E_PK[p * H_ + o];
        }
        const float* w = Wk + o * H_;
        #pragma unroll 4
        for (int k = 0; k < H_; k++) {
            float wv = w[k];
            #pragma unroll
            for (int rr = 0; rr < ROWS_PER_BLK; rr++) acc[rr] += xk[rr][k] * wv;
        }
        #pragma unroll
        for (int rr = 0; rr < ROWS_PER_BLK; rr++) g_K[(r0 + rr) * H_ + o] = acc[rr];
    }

    // ---- V ----
    {
        #pragma unroll
        for (int rr = 0; rr < ROWS_PER_BLK; rr++) {
            int p = poss[r0 + rr];
            acc[rr] = bv[o] + E_PV[p * H_ + o];
        }
        const float* w = Wv + o * H_;
        #pragma unroll 4
        for (int k = 0; k < H_; k++) {
            float wv = w[k];
            #pragma unroll
            for (int rr = 0; rr < ROWS_PER_BLK; rr++) acc[rr] += xv[rr][k] * wv;
        }
        #pragma unroll
        for (int rr = 0; rr < ROWS_PER_BLK; rr++) g_V[(r0 + rr) * H_ + o] = acc[rr];
    }
}

// ---------------------------------------------------------------------------
// Kernel 2: attention with relative-position key/value contributions.
// One block per (i, h, b). 256 threads.
//   scores[j] = ( q . (K_j + E_RK[iv[j]]) ) / 8     (causal: j <= i)
//   w = softmax(scores)
//   out[d]    = sum_j w[j] * (V_j[d] + E_RV[iv[j]][d])
// ---------------------------------------------------------------------------
__global__ __launch_bounds__(256) void attn_kernel(
    const float* __restrict__ E_RK, const float* __restrict__ E_RV,
    const int* __restrict__ interval)
{
    const int i = blockIdx.x;
    const int h = blockIdx.y;
    const int b = blockIdx.z;
    const int tid = threadIdx.x;

    __shared__ float qs[DH_];
    __shared__ float sc[L_];
    __shared__ int   idxs[L_];
    __shared__ float red[256];

    const int n = i + 1;   // valid keys (causal)
    const int hd = h * DH_;

    // Phase 1: load q
    if (tid < DH_)
        qs[tid] = g_Q[((b * L_ + i) * H_) + hd + tid];
    __syncthreads();

    // Phase 2: scores — warp per j, lanes over DH (2 elems/lane)
    {
        const int warp = tid >> 5;
        const int lane = tid & 31;
        const float* Kb = g_K + (size_t)b * L_ * H_ + hd;
        const int*   iv = interval + ((size_t)(b * L_ + i)) * L_;
        const float q0 = qs[lane], q1 = qs[lane + 32];

        for (int j = warp; j < n; j += 8) {
            int idx = iv[j];
            const float* kr = Kb + j * H_;
            const float* rk = E_RK + idx * H_ + hd;
            float p = q0 * (kr[lane] + rk[lane]) +
                      q1 * (kr[lane + 32] + rk[lane + 32]);
            #pragma unroll
            for (int off = 16; off > 0; off >>= 1)
                p += __shfl_xor_sync(0xffffffffu, p, off);
            if (lane == 0) {
                sc[j]   = p * 0.125f;   // 1/sqrt(64)
                idxs[j] = idx;
            }
        }
    }
    __syncthreads();

    // Phase 3: softmax over sc[0..n)
    {
        float m = -INFINITY;
        for (int j = tid; j < n; j += 256) m = fmaxf(m, sc[j]);
        red[tid] = m;
        __syncthreads();
        #pragma unroll
        for (int s = 128; s > 0; s >>= 1) {
            if (tid < s) red[tid] = fmaxf(red[tid], red[tid + s]);
            __syncthreads();
        }
        m = red[0];
        __syncthreads();

        float sum = 0.f;
        for (int j = tid; j < n; j += 256) {
            float e = __expf(sc[j] - m);
            sc[j] = e;
            sum += e;
        }
        red[tid] = sum;
        __syncthreads();
        #pragma unroll
        for (int s = 128; s > 0; s >>= 1) {
            if (tid < s) red[tid] += red[tid + s];
            __syncthreads();
        }
        float inv = 1.f / red[0];
        __syncthreads();
        for (int j = tid; j < n; j += 256) sc[j] *= inv;
    }
    __syncthreads();

    // Phase 4: output — 4 groups of 64 threads, thread owns dim d
    {
        const int d = tid & 63;
        const int g = tid >> 6;
        const float* Vb = g_V + (size_t)b * L_ * H_ + hd;
        float acc = 0.f;
        for (int j = g; j < n; j += 4) {
            float w = sc[j];
            int idx = idxs[j];
            acc += w * (Vb[j * H_ + d] + E_RV[idx * H_ + hd + d]);
        }
        red[g * 64 + d] = acc;
        __syncthreads();
        if (g == 0) {
            float o = red[d] + red[64 + d] + red[128 + d] + red[192 + d];
            g_O[((b * L_ + i) * H_) + hd + d] = o;
        }
    }
}

// ---------------------------------------------------------------------------
// Kernel 3: output projection: out = O @ Wo^T + bo, NaN -> 0
// ---------------------------------------------------------------------------
__global__ __launch_bounds__(128) void proj_kernel(
    const float* __restrict__ Wo, const float* __restrict__ bo,
    float* __restrict__ out)
{
    __shared__ float x[ROWS_PER_BLK][H_];
    const int r0 = blockIdx.x * ROWS_PER_BLK;
    const int o  = threadIdx.x;

    #pragma unroll
    for (int rr = 0; rr < ROWS_PER_BLK; rr++)
        x[rr][o] = g_O[(r0 + rr) * H_ + o];
    __syncthreads();

    float acc[ROWS_PER_BLK];
    float b = bo[o];
    #pragma unroll
    for (int rr = 0; rr < ROWS_PER_BLK; rr++) acc[rr] = b;

    const float* w = Wo + o * H_;
    #pragma unroll 4
    for (int k = 0; k < H_; k++) {
        float wv = w[k];
        #pragma unroll
        for (int rr = 0; rr < ROWS_PER_BLK; rr++) acc[rr] += x[rr][k] * wv;
    }

    #pragma unroll
    for (int rr = 0; rr < ROWS_PER_BLK; rr++) {
        float v = acc[rr];
        if (isnan(v)) v = 0.f;
        out[(r0 + rr) * H_ + o] = v;
    }
}

// ---------------------------------------------------------------------------
extern "C" void kernel_launch(void* const* d_in, const int* in_sizes, int n_in,
                              void* d_out, int out_size)
{
    const float* query    = (const float*)d_in[0];
    const float* key      = (const float*)d_in[1];
    const float* value    = (const float*)d_in[2];
    const float* Wq       = (const float*)d_in[3];
    const float* bq       = (const float*)d_in[4];
    const float* Wk       = (const float*)d_in[5];
    const float* bk       = (const float*)d_in[6];
    const float* Wv       = (const float*)d_in[7];
    const float* bv       = (const float*)d_in[8];
    const float* Wo       = (const float*)d_in[9];
    const float* bo       = (const float*)d_in[10];
    const float* E_PK     = (const float*)d_in[11];
    const float* E_PV     = (const float*)d_in[12];
    const float* E_RK     = (const float*)d_in[13];
    const float* E_RV     = (const float*)d_in[14];
    const int*   poss     = (const int*)d_in[15];
    const int*   interval = (const int*)d_in[16];
    // d_in[17] = attn_mask (exactly tril; causal is hardcoded)

    float* out = (float*)d_out;

    qkv_kernel<<<(B_ * L_) / ROWS_PER_BLK, 128>>>(
        query, key, value, Wq, bq, Wk, bk, Wv, bv, E_PK, E_PV, poss);

    dim3 agrid(L_, NH_, B_);
    attn_kernel<<<agrid, 256>>>(E_RK, E_RV, interval);

    proj_kernel<<<(B_ * L_) / ROWS_PER_BLK, 128>>>(Wo, bo, out);
}

// round 3
// speedup vs baseline: 1.0119x; 1.0119x over previous
#include <cuda_runtime.h>
#include <math.h>

#define B_  2
#define L_  512
#define H_  128
#define NH_ 2
#define DH_ 64

// Scratch (allocation-free rule: __device__ globals)
__device__ float g_Q[B_ * L_ * H_];
__device__ float g_K[B_ * L_ * H_];
__device__ float g_V[B_ * L_ * H_];
__device__ float g_O[B_ * L_ * H_];

#define ROWS_PER_BLK 8

// ---------------------------------------------------------------------------
// Kernel 1: fused QKV projections
//   Q = query @ Wq^T + bq
//   K = key   @ Wk^T + bk + E_PK[pos]
//   V = value @ Wv^T + bv + E_PV[pos]
// block = 128 threads (one per output channel o), 8 rows per block.
// ---------------------------------------------------------------------------
__global__ __launch_bounds__(128) void qkv_kernel(
    const float* __restrict__ query, const float* __restrict__ key,
    const float* __restrict__ value,
    const float* __restrict__ Wq, const float* __restrict__ bq,
    const float* __restrict__ Wk, const float* __restrict__ bk,
    const float* __restrict__ Wv, const float* __restrict__ bv,
    const float* __restrict__ E_PK, const float* __restrict__ E_PV,
    const int* __restrict__ poss)
{
    __shared__ float xq[ROWS_PER_BLK][H_];
    __shared__ float xk[ROWS_PER_BLK][H_];
    __shared__ float xv[ROWS_PER_BLK][H_];

    const int r0 = blockIdx.x * ROWS_PER_BLK;
    const int o  = threadIdx.x;   // 0..127

    #pragma unroll
    for (int rr = 0; rr < ROWS_PER_BLK; rr++) {
        int r = r0 + rr;
        xq[rr][o] = query[r * H_ + o];
        xk[rr][o] = key  [r * H_ + o];
        xv[rr][o] = value[r * H_ + o];
    }
    __syncthreads();

    float acc[ROWS_PER_BLK];

    // ---- Q ----
    {
        float b = bq[o];
        #pragma unroll
        for (int rr = 0; rr < ROWS_PER_BLK; rr++) acc[rr] = b;
        const float* w = Wq + o * H_;
        #pragma unroll 4
        for (int k = 0; k < H_; k++) {
            float wv = w[k];
            #pragma unroll
            for (int rr = 0; rr < ROWS_PER_BLK; rr++) acc[rr] += xq[rr][k] * wv;
        }
        #pragma unroll
        for (int rr = 0; rr < ROWS_PER_BLK; rr++) g_Q[(r0 + rr) * H_ + o] = acc[rr];
    }

    // ---- K ----
    {
        #pragma unroll
        for (int rr = 0; rr < ROWS_PER_BLK; rr++) {
            int p = poss[r0 + rr];
            acc[rr] = bk[o] + E_PK[p * H_ + o];
        }
        const float* w = Wk + o * H_;
        #pragma unroll 4
        for (int k = 0; k < H_; k++) {
            float wv = w[k];
            #pragma unroll
            for (int rr = 0; rr < ROWS_PER_BLK; rr++) acc[rr] += xk[rr][k] * wv;
        }
        #pragma unroll
        for (int rr = 0; rr < ROWS_PER_BLK; rr++) g_K[(r0 + rr) * H_ + o] = acc[rr];
    }

    // ---- V ----
    {
        #pragma unroll
        for (int rr = 0; rr < ROWS_PER_BLK; rr++) {
            int p = poss[r0 + rr];
            acc[rr] = bv[o] + E_PV[p * H_ + o];
        }
        const float* w = Wv + o * H_;
        #pragma unroll 4
        for (int k = 0; k < H_; k++) {
            float wv = w[k];
            #pragma unroll
            for (int rr = 0; rr < ROWS_PER_BLK; rr++) acc[rr] += xv[rr][k] * wv;
        }
        #pragma unroll
        for (int rr = 0; rr < ROWS_PER_BLK; rr++) g_V[(r0 + rr) * H_ + o] = acc[rr];
    }
}

// ---------------------------------------------------------------------------
// Kernel 2: attention with relative-position key/value contributions.
// One block per (i, h, b). 256 threads.
//   scores[j] = ( q . (K_j + E_RK[iv[j]]) ) / 8     (causal: j <= i)
//   w = softmax(scores)
//   out[d]    = sum_j w[j] * (V_j[d] + E_RV[iv[j]][d])
// ---------------------------------------------------------------------------
__global__ __launch_bounds__(256) void attn_kernel(
    const float* __restrict__ E_RK, const float* __restrict__ E_RV,
    const int* __restrict__ interval)
{
    const int i = blockIdx.x;
    const int h = blockIdx.y;
    const int b = blockIdx.z;
    const int tid = threadIdx.x;

    __shared__ float qs[DH_];
    __shared__ float sc[L_];
    __shared__ int   idxs[L_];
    __shared__ float red[256];

    const int n = i + 1;   // valid keys (causal)
    const int hd = h * DH_;

    // Phase 1: load q
    if (tid < DH_)
        qs[tid] = g_Q[((b * L_ + i) * H_) + hd + tid];
    __syncthreads();

    // Phase 2: scores — warp per j, lanes over DH (2 elems/lane)
    {
        const int warp = tid >> 5;
        const int lane = tid & 31;
        const float* Kb = g_K + (size_t)b * L_ * H_ + hd;
        const int*   iv = interval + ((size_t)(b * L_ + i)) * L_;
        const float q0 = qs[lane], q1 = qs[lane + 32];

        for (int j = warp; j < n; j += 8) {
            int idx = iv[j];
            const float* kr = Kb + j * H_;
            const float* rk = E_RK + idx * H_ + hd;
            float p = q0 * (kr[lane] + rk[lane]) +
                      q1 * (kr[lane + 32] + rk[lane + 32]);
            #pragma unroll
            for (int off = 16; off > 0; off >>= 1)
                p += __shfl_xor_sync(0xffffffffu, p, off);
            if (lane == 0) {
                sc[j]   = p * 0.125f;   // 1/sqrt(64)
                idxs[j] = idx;
            }
        }
    }
    __syncthreads();

    // Phase 3: softmax over sc[0..n)
    {
        float m = -INFINITY;
        for (int j = tid; j < n; j += 256) m = fmaxf(m, sc[j]);
        red[tid] = m;
        __syncthreads();
        #pragma unroll
        for (int s = 128; s > 0; s >>= 1) {
            if (tid < s) red[tid] = fmaxf(red[tid], red[tid + s]);
            __syncthreads();
        }
        m = red[0];
        __syncthreads();

        float sum = 0.f;
        for (int j = tid; j < n; j += 256) {
            float e = __expf(sc[j] - m);
            sc[j] = e;
            sum += e;
        }
        red[tid] = sum;
        __syncthreads();
        #pragma unroll
        for (int s = 128; s > 0; s >>= 1) {
            if (tid < s) red[tid] += red[tid + s];
            __syncthreads();
        }
        float inv = 1.f / red[0];
        __syncthreads();
        for (int j = tid; j < n; j += 256) sc[j] *= inv;
    }
    __syncthreads();

    // Phase 4: output — 4 groups of 64 threads, thread owns dim d
    {
        const int d = tid & 63;
        const int g = tid >> 6;
        const float* Vb = g_V + (size_t)b * L_ * H_ + hd;
        float acc = 0.f;
        for (int j = g; j < n; j += 4) {
            float w = sc[j];
            int idx = idxs[j];
            acc += w * (Vb[j * H_ + d] + E_RV[idx * H_ + hd + d]);
        }
        red[g * 64 + d] = acc;
        __syncthreads();
        if (g == 0) {
            float o = red[d] + red[64 + d] + red[128 + d] + red[192 + d];
            g_O[((b * L_ + i) * H_) + hd + d] = o;
        }
    }
}

// ---------------------------------------------------------------------------
// Kernel 3: output projection: out = O @ Wo^T + bo, NaN -> 0
// ---------------------------------------------------------------------------
__global__ __launch_bounds__(128) void proj_kernel(
    const float* __restrict__ Wo, const float* __restrict__ bo,
    float* __restrict__ out)
{
    __shared__ float x[ROWS_PER_BLK][H_];
    const int r0 = blockIdx.x * ROWS_PER_BLK;
    const int o  = threadIdx.x;

    #pragma unroll
    for (int rr = 0; rr < ROWS_PER_BLK; rr++)
        x[rr][o] = g_O[(r0 + rr) * H_ + o];
    __syncthreads();

    float acc[ROWS_PER_BLK];
    float b = bo[o];
    #pragma unroll
    for (int rr = 0; rr < ROWS_PER_BLK; rr++) acc[rr] = b;

    const float* w = Wo + o * H_;
    #pragma unroll 4
    for (int k = 0; k < H_; k++) {
        float wv = w[k];
        #pragma unroll
        for (int rr = 0; rr < ROWS_PER_BLK; rr++) acc[rr] += x[rr][k] * wv;
    }

    #pragma unroll
    for (int rr = 0; rr < ROWS_PER_BLK; rr++) {
        float v = acc[rr];
        if (isnan(v)) v = 0.f;
        out[(r0 + rr) * H_ + o] = v;
    }
}

// ---------------------------------------------------------------------------
extern "C" void kernel_launch(void* const* d_in, const int* in_sizes, int n_in,
                              void* d_out, int out_size)
{
    const float* query    = (const float*)d_in[0];
    const float* key      = (const float*)d_in[1];
    const float* value    = (const float*)d_in[2];
    const float* Wq       = (const float*)d_in[3];
    const float* bq       = (const float*)d_in[4];
    const float* Wk       = (const float*)d_in[5];
    const float* bk       = (const float*)d_in[6];
    const float* Wv       = (const float*)d_in[7];
    const float* bv       = (const float*)d_in[8];
    const float* Wo       = (const float*)d_in[9];
    const float* bo       = (const float*)d_in[10];
    const float* E_PK     = (const float*)d_in[11];
    const float* E_PV     = (const float*)d_in[12];
    const float* E_RK     = (const float*)d_in[13];
    const float* E_RV     = (const float*)d_in[14];
    const int*   poss     = (const int*)d_in[15];
    const int*   interval = (const int*)d_in[16];
    // d_in[17] = attn_mask (exactly tril; causal is hardcoded)

    float* out = (float*)d_out;

    qkv_kernel<<<(B_ * L_) / ROWS_PER_BLK, 128>>>(
        query, key, value, Wq, bq, Wk, bk, Wv, bv, E_PK, E_PV, poss);

    dim3 agrid(L_, NH_, B_);
    attn_kernel<<<agrid, 256>>>(E_RK, E_RV, interval);

    proj_kernel<<<(B_ * L_) / ROWS_PER_BLK, 128>>>(Wo, bo, out);
}